// round 12
// baseline (speedup 1.0000x reference)
#include <cuda_runtime.h>

// Problem constants (fixed by the reference)
#define BATCH 16
#define MCTRL 64          // control points per dim
#define DEG   3           // degree P == Q
#define KLEN  68          // MCTRL + DEG + 1 knots
#define NSPAN 62          // KLEN - 2*DEG candidate spans
#define TPTS  256         // OUT_U == OUT_V
#define IPB   4           // output rows (i values) per block

// ---------------------------------------------------------------------------
// Per-thread basis: binary-search span + Cox-de Boor (deg 3), the reference's
// arithmetic (fast division; error ~1e-7 vs 1e-3 tolerance).
// Span = argmin over cand[s] = (tp-U[3+s] > 1e-8) ? tp-U[3+s] : 1.
// U[3..64] strictly increasing -> d strictly decreasing -> minimum is the
// LAST s with d > 1e-8 -> 6-step binary search. s=0 always valid.
// ---------------------------------------------------------------------------
__device__ __forceinline__ void basis_at(const float* __restrict__ U,
                                         float tp, float N[DEG + 1], int& span)
{
    int lo = 0, hi = NSPAN - 1;
    #pragma unroll
    for (int it = 0; it < 6; it++) {           // ceil(log2(62)) = 6
        const int mid = (lo + hi + 1) >> 1;
        if (lo < hi) {
            if (tp - U[DEG + mid] > 1e-8f) lo = mid; else hi = mid - 1;
        }
    }
    span = lo + DEG;

    N[0] = 1.0f;
    #pragma unroll
    for (int k = 1; k <= DEG; k++) {
        float saved = 0.0f;
        #pragma unroll
        for (int r = 0; r < k; r++) {
            const float K1 = U[span + r + 1];
            const float K2 = U[span + 1 - k + r];
            const float temp = __fdividef(N[r], (K1 - tp) + (tp - K2));
            N[r] = saved + (K1 - tp) * temp;
            saved = (tp - K2) * temp;
        }
        N[k] = saved;
    }
}

// 32-lane inclusive scan via shfl
__device__ __forceinline__ float warp_iscan(float v, int lane) {
    #pragma unroll
    for (int off = 1; off < 32; off <<= 1) {
        const float t = __shfl_up_sync(0xffffffffu, v, off);
        if (lane >= off) v += t;
    }
    return v;
}

// ---------------------------------------------------------------------------
// Fused kernel. Block = (i-tile of IPB=4 rows, batch b), 256 threads.
//   0) warp-0 shuffle scan of the 68 knots -> normalized U in smem
//      (Nv==Nu: the reference builds V from knot_u too, and u==v).
//   1) thread j: basis for eval point j -> smem table wvtab/col0tab.
//      Row bases for rows i0..i0+3 ARE table entries i0..i0+3 (u==v).
//   2) row blend straight from global (coalesced LDG.32, L2-resident ctrl):
//      thread (col,comp): blend[k][col].comp = sum_l wu[l]*ctrl[row0+l][col].comp
//   3) stencil with warp<->row mapping: each warp owns ONE row k and 4
//      groups of 32 CONSECUTIVE j (lanes j=base+lane). Consecutive-j lanes
//      share ~8 distinct col0 values -> LDS.128 broadcast-dedup (~2
//      wavefronts instead of 4). 3 STG.32 per group (direct, as R4).
// ---------------------------------------------------------------------------
__global__ void __launch_bounds__(TPTS) fused_kernel(
    const float4* __restrict__ ctrl,     // [B][64][64] float4
    const float*  __restrict__ knot_u,   // [B][68]
    float*        __restrict__ out)      // [B][256][256][3]
{
    const int b  = blockIdx.y;
    const int i0 = blockIdx.x * IPB;
    const int j  = threadIdx.x;

    __shared__ float  U[KLEN];
    __shared__ float4 wvtab[TPTS];            // 4 KB basis table
    __shared__ int    c0tab[TPTS];            // 1 KB window starts
    __shared__ float4 blend[IPB][MCTRL];      // 4 KB

    // --- Stage 0: warp-0 scan of knots + normalize ---
    if (j < 32) {
        const float* kb = knot_u + b * KLEN;
        float a0 = kb[j];
        float a1 = kb[j + 32];
        float a2 = (j < KLEN - 64) ? kb[j + 64] : 0.0f;
        const float k0 = __shfl_sync(0xffffffffu, a0, 0);  // knot[0]

        a0 = warp_iscan(a0, j);
        const float tot0 = __shfl_sync(0xffffffffu, a0, 31);
        a1 = warp_iscan(a1, j) + tot0;
        const float tot1 = __shfl_sync(0xffffffffu, a1, 31);
        a2 = warp_iscan(a2, j) + tot1;

        const float last = __shfl_sync(0xffffffffu, a2, KLEN - 64 - 1); // c[67]
        const float inv  = 1.0f / (last - k0);
        U[j]      = (a0 - k0) * inv;
        U[j + 32] = (a1 - k0) * inv;
        if (j < KLEN - 64) U[j + 64] = (a2 - k0) * inv;
    }
    __syncthreads();

    // --- Stage 1: per-thread basis -> table ---
    {
        const float tp = 1e-5f + (float)j * ((1.0f - 2e-5f) / 255.0f);
        float N[DEG + 1];
        int   span;
        basis_at(U, tp, N, span);
        int c0 = span - DEG;
        c0 = c0 < 0 ? 0 : (c0 > MCTRL - 4 ? MCTRL - 4 : c0);
        wvtab[j] = make_float4(N[0], N[1], N[2], N[3]);
        c0tab[j] = c0;
    }
    __syncthreads();

    // --- Stage 2: row blends straight from global ---
    // thread j <-> (col = j>>2, comp = j&3); float offset col*4+comp == j,
    // so each row read is a fully-coalesced 128B warp transaction (L2 hit).
    {
        const float* cbase = (const float*)ctrl + b * (MCTRL * MCTRL * 4);
        #pragma unroll
        for (int k = 0; k < IPB; k++) {
            const float4 wu = wvtab[i0 + k];          // broadcast LDS
            const int    r0 = c0tab[i0 + k];
            const float* rp = cbase + r0 * (MCTRL * 4) + j;
            float acc;
            acc = wu.x * rp[0];
            acc = fmaf(wu.y, rp[1 * MCTRL * 4], acc);
            acc = fmaf(wu.z, rp[2 * MCTRL * 4], acc);
            acc = fmaf(wu.w, rp[3 * MCTRL * 4], acc);
            ((float*)blend)[k * MCTRL * 4 + j] = acc;   // blend[k][col].comp
        }
    }
    __syncthreads();

    // --- Stage 3: stencil. warp -> one row; 4 groups of 32 consecutive j ---
    {
        const int k = j >> 6;          // row index within tile (2 warps/row)
        const int u = j & 63;          // position within row-group
        const int rowbase = (b * TPTS + i0 + k) * (TPTS * 3);

        #pragma unroll
        for (int m = 0; m < 4; m++) {
            const int jj = m * 64 + u;            // warp lanes: consecutive jj
            const float4 wv = wvtab[jj];          // LDS.128, consecutive
            const int    c0 = c0tab[jj];

            const float4 q0 = blend[k][c0 + 0];   // dedup-friendly gathers
            const float4 q1 = blend[k][c0 + 1];
            const float4 q2 = blend[k][c0 + 2];
            const float4 q3 = blend[k][c0 + 3];

            const float x =
                fmaf(wv.x, q0.x, fmaf(wv.y, q1.x, fmaf(wv.z, q2.x, wv.w * q3.x)));
            const float y =
                fmaf(wv.x, q0.y, fmaf(wv.y, q1.y, fmaf(wv.z, q2.y, wv.w * q3.y)));
            const float z =
                fmaf(wv.x, q0.z, fmaf(wv.y, q1.z, fmaf(wv.z, q2.z, wv.w * q3.z)));

            const int base = rowbase + jj * 3;    // 32-bit indexing
            out[base + 0] = x;
            out[base + 1] = y;
            out[base + 2] = z;
        }
    }
}

// ---------------------------------------------------------------------------
// Launch: single fused kernel (knot_v is unused — the reference builds V
// from knot_u as well).
// ---------------------------------------------------------------------------
extern "C" void kernel_launch(void* const* d_in, const int* in_sizes, int n_in,
                              void* d_out, int out_size) {
    const float* ctrl   = (const float*)d_in[0];   // [16,64,64,4] f32
    const float* knot_u = (const float*)d_in[1];   // [16,68] f32
    (void)in_sizes; (void)n_in; (void)out_size;

    fused_kernel<<<dim3(TPTS / IPB, BATCH), TPTS>>>(
        (const float4*)ctrl, knot_u, (float*)d_out);
}